// round 1
// baseline (speedup 1.0000x reference)
#include <cuda_runtime.h>
#include <cstdint>

// Problem constants
static constexpr int B_   = 8;
static constexpr int N_   = 16384;
static constexpr int S_   = 2048;
static constexpr int C1_  = 128;
static constexpr int C2_  = 256;
static constexpr int K1_  = 384;   // C1 + C2
static constexpr int O_   = 256;   // both MLP layers output 256
static constexpr float BN_EPS = 1e-5f;
static constexpr float CNT_INV = 1.0f / (float)(B_ * N_);  // 1/131072

// ---------------- scratch (device globals; no cudaMalloc allowed) -------------
__device__ float g_interp[(size_t)B_ * C2_ * N_];   // interp [B][256][N]; reused as y2
__device__ float g_y[(size_t)B_ * O_ * N_];         // y1 (pre-BN GEMM1 out)
__device__ float g_p2t[(size_t)B_ * S_ * C2_];      // points2 transposed [B][S][C]
__device__ int   g_idx[(size_t)B_ * N_ * 3];
__device__ float g_w[(size_t)B_ * N_ * 3];
__device__ float g_part[2 * 256 * 64];              // stage-1 partial sums / sumsq
__device__ float g_sb1[512];                        // layer1 fused scale/bias
__device__ float g_sb2[512];                        // layer2 fused scale/bias

// ---------------- f32x2 packed math helpers ----------------------------------
typedef unsigned long long u64_t;
__device__ __forceinline__ u64_t pack2(float lo, float hi) {
    u64_t r;
    asm("mov.b64 %0, {%1, %2};" : "=l"(r) : "f"(lo), "f"(hi));
    return r;
}
__device__ __forceinline__ void ffma2(u64_t& acc, u64_t a, u64_t b) {
    asm("fma.rn.f32x2 %0, %1, %2, %3;" : "=l"(acc) : "l"(a), "l"(b), "l"(acc));
}
__device__ __forceinline__ float2 unpack2(u64_t v) {
    float2 r;
    asm("mov.b64 {%0, %1}, %2;" : "=f"(r.x), "=f"(r.y) : "l"(v));
    return r;
}

// ---------------- kNN: top-3 nearest + normalized inverse-distance weights ----
__global__ __launch_bounds__(256) void knn_kernel(
    const float* __restrict__ xyz1, const float* __restrict__ xyz2)
{
    __shared__ float4 sp[S_];
    const int b = blockIdx.y;
    const int t = threadIdx.x;
    for (int s = t; s < S_; s += 256) {
        const float* p = xyz2 + ((size_t)b * S_ + s) * 3;
        sp[s] = make_float4(p[0], p[1], p[2], 0.0f);
    }
    __syncthreads();

    const int n = blockIdx.x * 256 + t;
    const float* q = xyz1 + ((size_t)b * N_ + n) * 3;
    const float qx = q[0], qy = q[1], qz = q[2];

    float d0 = 3.4e38f, d1 = 3.4e38f, d2 = 3.4e38f;
    int   i0 = 0, i1 = 0, i2 = 0;
    #pragma unroll 4
    for (int s = 0; s < S_; s++) {
        float4 p = sp[s];
        float dx = qx - p.x, dy = qy - p.y, dz = qz - p.z;
        float d = fmaf(dz, dz, fmaf(dy, dy, dx * dx));
        if (d < d2) {
            if (d < d1) {
                d2 = d1; i2 = i1;
                if (d < d0) { d1 = d0; i1 = i0; d0 = d; i0 = s; }
                else        { d1 = d;  i1 = s; }
            } else { d2 = d; i2 = s; }
        }
    }
    d0 = fmaxf(d0, 1e-10f);
    d1 = fmaxf(d1, 1e-10f);
    d2 = fmaxf(d2, 1e-10f);
    float w0 = 1.0f / d0, w1 = 1.0f / d1, w2 = 1.0f / d2;
    float sw = w0 + w1 + w2;
    size_t base = ((size_t)b * N_ + n) * 3;
    g_idx[base + 0] = i0; g_idx[base + 1] = i1; g_idx[base + 2] = i2;
    g_w[base + 0] = w0 / sw; g_w[base + 1] = w1 / sw; g_w[base + 2] = w2 / sw;
}

// ---------------- transpose points2 [B][C][S] -> [B][S][C] --------------------
__global__ void transpose_p2_kernel(const float* __restrict__ p2)
{
    __shared__ float tile[32][33];
    const int b  = blockIdx.z;
    const int s0 = blockIdx.x * 32;
    const int c0 = blockIdx.y * 32;
    #pragma unroll
    for (int r = 0; r < 4; r++) {
        int c = c0 + threadIdx.y + r * 8;
        tile[threadIdx.y + r * 8][threadIdx.x] =
            p2[((size_t)b * C2_ + c) * S_ + s0 + threadIdx.x];
    }
    __syncthreads();
    #pragma unroll
    for (int r = 0; r < 4; r++) {
        int s = s0 + threadIdx.y + r * 8;
        g_p2t[((size_t)b * S_ + s) * C2_ + c0 + threadIdx.x] =
            tile[threadIdx.x][threadIdx.y + r * 8];
    }
}

// ---------------- gather + weighted sum -> g_interp [B][256][N] ---------------
__global__ __launch_bounds__(256) void gather_kernel()
{
    __shared__ float sh[32][257];
    const int b  = blockIdx.y;
    const int n0 = blockIdx.x * 32;
    const int t  = threadIdx.x;

    #pragma unroll 2
    for (int nl = 0; nl < 32; nl++) {
        size_t base = ((size_t)b * N_ + n0 + nl) * 3;
        int i0 = g_idx[base], i1 = g_idx[base + 1], i2 = g_idx[base + 2];
        float w0 = g_w[base], w1 = g_w[base + 1], w2 = g_w[base + 2];
        const float* r0 = g_p2t + ((size_t)b * S_ + i0) * C2_;
        const float* r1 = g_p2t + ((size_t)b * S_ + i1) * C2_;
        const float* r2 = g_p2t + ((size_t)b * S_ + i2) * C2_;
        sh[nl][t] = fmaf(w2, r2[t], fmaf(w1, r1[t], w0 * r0[t]));
    }
    __syncthreads();
    #pragma unroll 4
    for (int it = 0; it < 32; it++) {
        int c  = it * 8 + (t >> 5);
        int nl = t & 31;
        g_interp[((size_t)b * C2_ + c) * N_ + n0 + nl] = sh[nl][c];
    }
}

// ---------------- GEMM (fp32, packed f32x2 FMA) -------------------------------
// MODE 0: y1 = W0 @ concat(interp, points1) + b0   (K=384)
// MODE 1: y2 = W1 @ relu(sb1_scale*y1 + sb1_bias) + b1  (K=256, norm fused in load)
template<int MODE>
__global__ __launch_bounds__(256, 2) void gemm_kernel(
    const float* __restrict__ A,      // W [256 x K]
    const float* __restrict__ bias,   // [256]
    const float* __restrict__ Bmain,  // MODE0: g_interp ; MODE1: g_y (y1)
    const float* __restrict__ Baux,   // MODE0: points1 ; MODE1: unused
    const float* __restrict__ sb,     // MODE1: g_sb1
    float* __restrict__ C)
{
    constexpr int K = (MODE == 0) ? K1_ : O_;
    __shared__ float As[16][128];
    __shared__ float Bs[16][128];

    const int t  = threadIdx.x;
    const int b  = blockIdx.z;
    const int m0 = blockIdx.y * 128;
    const int n0 = blockIdx.x * 128;

    const int ar = ((t + 0) >> 2);        // A row within tile for pass 0 (pass1: +64)
    const int aq = t & 3;                 // A float4 column group
    const int bk = t >> 5;                // B k-row for pass 0 (pass1: +8)
    const int bq = t & 31;                // B float4 column group

    float4 ra[2], rb[2];

    auto loadA = [&](int kt) {
        #pragma unroll
        for (int p = 0; p < 2; p++) {
            int row = ar + p * 64;
            ra[p] = *(const float4*)(A + (size_t)(m0 + row) * K + kt + aq * 4);
        }
    };
    auto loadB = [&](int kt) {
        #pragma unroll
        for (int p = 0; p < 2; p++) {
            int k = bk + p * 8;
            int c = kt + k;
            if (MODE == 0) {
                const float* src = (c < C2_)
                    ? (Bmain + ((size_t)b * C2_ + c) * N_)
                    : (Baux  + ((size_t)b * C1_ + (c - C2_)) * N_);
                rb[p] = *(const float4*)(src + n0 + bq * 4);
            } else {
                const float* src = Bmain + ((size_t)b * O_ + c) * N_;
                float4 v = *(const float4*)(src + n0 + bq * 4);
                float sc = __ldg(sb + c), bs = __ldg(sb + 256 + c);
                v.x = fmaxf(fmaf(v.x, sc, bs), 0.0f);
                v.y = fmaxf(fmaf(v.y, sc, bs), 0.0f);
                v.z = fmaxf(fmaf(v.z, sc, bs), 0.0f);
                v.w = fmaxf(fmaf(v.w, sc, bs), 0.0f);
                rb[p] = v;
            }
        }
    };

    u64_t acc[8][4];
    #pragma unroll
    for (int i = 0; i < 8; i++)
        #pragma unroll
        for (int j = 0; j < 4; j++) acc[i][j] = 0ull;

    const int ty = t >> 5;   // m group (16 rows)
    const int tx = t & 31;   // n group (4 cols)

    loadA(0); loadB(0);

    for (int kt = 0; kt < K; kt += 16) {
        __syncthreads();
        #pragma unroll
        for (int p = 0; p < 2; p++) {
            int row = ar + p * 64;
            As[aq * 4 + 0][row] = ra[p].x;
            As[aq * 4 + 1][row] = ra[p].y;
            As[aq * 4 + 2][row] = ra[p].z;
            As[aq * 4 + 3][row] = ra[p].w;
            *(float4*)&Bs[bk + p * 8][bq * 4] = rb[p];
        }
        __syncthreads();
        if (kt + 16 < K) { loadA(kt + 16); loadB(kt + 16); }

        #pragma unroll
        for (int k = 0; k < 16; k++) {
            u64_t av[8];
            const u64_t* ap = (const u64_t*)&As[k][ty * 16];
            #pragma unroll
            for (int i = 0; i < 8; i++) av[i] = ap[i];
            float4 bv = *(const float4*)&Bs[k][tx * 4];
            u64_t bd[4];
            bd[0] = pack2(bv.x, bv.x);
            bd[1] = pack2(bv.y, bv.y);
            bd[2] = pack2(bv.z, bv.z);
            bd[3] = pack2(bv.w, bv.w);
            #pragma unroll
            for (int i = 0; i < 8; i++)
                #pragma unroll
                for (int j = 0; j < 4; j++)
                    ffma2(acc[i][j], av[i], bd[j]);
        }
    }

    const int gn = n0 + tx * 4;
    #pragma unroll
    for (int i = 0; i < 8; i++) {
        float2 u0 = unpack2(acc[i][0]);
        float2 u1 = unpack2(acc[i][1]);
        float2 u2 = unpack2(acc[i][2]);
        float2 u3 = unpack2(acc[i][3]);
        int r0 = m0 + ty * 16 + 2 * i;
        int r1 = r0 + 1;
        float bv0 = __ldg(bias + r0), bv1 = __ldg(bias + r1);
        float4 o0 = make_float4(u0.x + bv0, u1.x + bv0, u2.x + bv0, u3.x + bv0);
        float4 o1 = make_float4(u0.y + bv1, u1.y + bv1, u2.y + bv1, u3.y + bv1);
        *(float4*)(C + ((size_t)b * O_ + r0) * N_ + gn) = o0;
        *(float4*)(C + ((size_t)b * O_ + r1) * N_ + gn) = o1;
    }
}

// ---------------- BN stats stage 1: per-channel partial sums ------------------
__global__ __launch_bounds__(256) void stats1_kernel(const float* __restrict__ y)
{
    const int o = blockIdx.x, j = blockIdx.y;
    const int b = j >> 3, seg = j & 7;
    const float* p = y + ((size_t)b * O_ + o) * N_ + seg * 2048;
    const int t = threadIdx.x;

    float s = 0.0f, ss = 0.0f;
    #pragma unroll
    for (int i = 0; i < 8; i++) {
        float v = p[t + i * 256];
        s += v;
        ss = fmaf(v, v, ss);
    }
    const int lane = t & 31, w = t >> 5;
    #pragma unroll
    for (int off = 16; off; off >>= 1) {
        s  += __shfl_down_sync(0xffffffffu, s,  off);
        ss += __shfl_down_sync(0xffffffffu, ss, off);
    }
    __shared__ float rs[8], rss[8];
    if (lane == 0) { rs[w] = s; rss[w] = ss; }
    __syncthreads();
    if (t == 0) {
        float ts = 0.0f, tss = 0.0f;
        #pragma unroll
        for (int i = 0; i < 8; i++) { ts += rs[i]; tss += rss[i]; }
        g_part[o * 64 + j]         = ts;
        g_part[16384 + o * 64 + j] = tss;
    }
}

// ---------------- BN stats stage 2: fold into scale/bias ----------------------
__global__ void stats2_kernel(const float* __restrict__ g,
                              const float* __restrict__ beta,
                              float* __restrict__ sb)
{
    const int o = blockIdx.x;
    const int t = threadIdx.x;  // 32
    float s  = g_part[o * 64 + t]         + g_part[o * 64 + t + 32];
    float ss = g_part[16384 + o * 64 + t] + g_part[16384 + o * 64 + t + 32];
    #pragma unroll
    for (int off = 16; off; off >>= 1) {
        s  += __shfl_down_sync(0xffffffffu, s,  off);
        ss += __shfl_down_sync(0xffffffffu, ss, off);
    }
    if (t == 0) {
        float mean = s * CNT_INV;
        float var  = ss * CNT_INV - mean * mean;
        float rstd = rsqrtf(var + BN_EPS);
        float sc = g[o] * rstd;
        sb[o]       = sc;
        sb[256 + o] = beta[o] - mean * sc;
    }
}

// ---------------- final normalize + relu -> d_out -----------------------------
__global__ __launch_bounds__(256) void normout_kernel(
    const float* __restrict__ y, const float* __restrict__ sb,
    float* __restrict__ out)
{
    size_t i4 = (size_t)blockIdx.x * 256 + threadIdx.x;
    int o = (int)((i4 >> 12) & 255);  // N/4 = 4096 = 2^12
    float sc = __ldg(sb + o), bs = __ldg(sb + 256 + o);
    float4 v = ((const float4*)y)[i4];
    v.x = fmaxf(fmaf(v.x, sc, bs), 0.0f);
    v.y = fmaxf(fmaf(v.y, sc, bs), 0.0f);
    v.z = fmaxf(fmaf(v.z, sc, bs), 0.0f);
    v.w = fmaxf(fmaf(v.w, sc, bs), 0.0f);
    ((float4*)out)[i4] = v;
}

// ---------------- launcher ----------------------------------------------------
extern "C" void kernel_launch(void* const* d_in, const int* in_sizes, int n_in,
                              void* d_out, int out_size)
{
    const float* xyz1  = (const float*)d_in[0];
    const float* xyz2  = (const float*)d_in[1];
    const float* pts1  = (const float*)d_in[2];
    const float* pts2  = (const float*)d_in[3];
    const float* W0    = (const float*)d_in[4];
    const float* b0    = (const float*)d_in[5];
    const float* gg0   = (const float*)d_in[6];
    const float* be0   = (const float*)d_in[7];
    const float* W1    = (const float*)d_in[8];
    const float* b1    = (const float*)d_in[9];
    const float* gg1   = (const float*)d_in[10];
    const float* be1   = (const float*)d_in[11];
    float* out = (float*)d_out;

    float* interp_p; cudaGetSymbolAddress((void**)&interp_p, g_interp);
    float* y_p;      cudaGetSymbolAddress((void**)&y_p, g_y);
    float* sb1_p;    cudaGetSymbolAddress((void**)&sb1_p, g_sb1);
    float* sb2_p;    cudaGetSymbolAddress((void**)&sb2_p, g_sb2);

    knn_kernel<<<dim3(N_ / 256, B_), 256>>>(xyz1, xyz2);
    transpose_p2_kernel<<<dim3(S_ / 32, C2_ / 32, B_), dim3(32, 8)>>>(pts2);
    gather_kernel<<<dim3(N_ / 32, B_), 256>>>();

    // layer 1 GEMM -> y1
    gemm_kernel<0><<<dim3(N_ / 128, 2, B_), 256>>>(W0, b0, interp_p, pts1, nullptr, y_p);
    stats1_kernel<<<dim3(256, 64), 256>>>(y_p);
    stats2_kernel<<<256, 32>>>(gg0, be0, sb1_p);

    // layer 2 GEMM (normalize+relu of y1 fused into B-load) -> y2 (reuses g_interp)
    gemm_kernel<1><<<dim3(N_ / 128, 2, B_), 256>>>(W1, b1, y_p, nullptr, sb1_p, interp_p);
    stats1_kernel<<<dim3(256, 64), 256>>>(interp_p);
    stats2_kernel<<<256, 32>>>(gg1, be1, sb2_p);

    normout_kernel<<<(B_ * O_ * N_) / 4 / 256, 256>>>(interp_p, sb2_p, out);
}

// round 3
// speedup vs baseline: 1.2338x; 1.2338x over previous
#include <cuda_runtime.h>
#include <cuda_bf16.h>
#include <cstdint>

static constexpr int B_  = 8;
static constexpr int N_  = 16384;
static constexpr int S_  = 2048;
static constexpr int C1_ = 128;
static constexpr int C2_ = 256;
static constexpr int K1_ = 384;
static constexpr int O_  = 256;
static constexpr float BN_EPS  = 1e-5f;
static constexpr float CNT_INV = 1.0f / (float)(B_ * N_);

// ---------------- device-global scratch (no cudaMalloc allowed) ---------------
__device__ __nv_bfloat16 g_xh[(size_t)B_ * N_ * K1_];   // concat input, bf16 hi
__device__ __nv_bfloat16 g_xl[(size_t)B_ * N_ * K1_];   // concat input, bf16 lo
__device__ float         g_y [(size_t)B_ * N_ * O_];    // y1 then y2 (n-major)
__device__ __nv_bfloat16 g_hh[(size_t)B_ * N_ * O_];    // layer2 input hi
__device__ __nv_bfloat16 g_hl[(size_t)B_ * N_ * O_];    // layer2 input lo
__device__ float         g_p2t[(size_t)B_ * S_ * C2_];  // points2 transposed [B][S][C]
__device__ int           g_idx[(size_t)B_ * N_ * 3];
__device__ float         g_w  [(size_t)B_ * N_ * 3];
__device__ __nv_bfloat16 g_w0h[O_ * K1_], g_w0l[O_ * K1_];
__device__ __nv_bfloat16 g_w1h[O_ * O_],  g_w1l[O_ * O_];
__device__ float         g_psum[256 * 1024], g_pssq[256 * 1024];
__device__ float         g_sb1[512], g_sb2[512];

// ---------------- small PTX helpers ------------------------------------------
__device__ __forceinline__ uint32_t smem_u32(const void* p) {
    uint32_t a;
    asm("{ .reg .u64 t; cvta.to.shared.u64 t, %1; cvt.u32.u64 %0, t; }"
        : "=r"(a) : "l"(p));
    return a;
}
__device__ __forceinline__ void cpa16(uint32_t dst, const void* src) {
    asm volatile("cp.async.cg.shared.global [%0], [%1], 16;"
                 :: "r"(dst), "l"(src) : "memory");
}
#define CP_COMMIT() asm volatile("cp.async.commit_group;" ::: "memory")
#define CP_WAIT0()  asm volatile("cp.async.wait_group 0;" ::: "memory")
#define CP_WAIT1()  asm volatile("cp.async.wait_group 1;" ::: "memory")

__device__ __forceinline__ void ldsm4(uint32_t addr, uint32_t* r) {
    asm volatile("ldmatrix.sync.aligned.m8n8.x4.shared.b16 {%0,%1,%2,%3}, [%4];"
                 : "=r"(r[0]), "=r"(r[1]), "=r"(r[2]), "=r"(r[3]) : "r"(addr));
}
__device__ __forceinline__ void mma16816(float* c, const uint32_t* a, const uint32_t* b) {
    asm volatile(
        "mma.sync.aligned.m16n8k16.row.col.f32.bf16.bf16.f32 "
        "{%0,%1,%2,%3}, {%4,%5,%6,%7}, {%8,%9}, {%0,%1,%2,%3};"
        : "+f"(c[0]), "+f"(c[1]), "+f"(c[2]), "+f"(c[3])
        : "r"(a[0]), "r"(a[1]), "r"(a[2]), "r"(a[3]), "r"(b[0]), "r"(b[1]));
}

// bf16 split helpers
__device__ __forceinline__ void bf16_split(float v, __nv_bfloat16& hi, __nv_bfloat16& lo) {
    hi = __float2bfloat16_rn(v);
    lo = __float2bfloat16_rn(v - __bfloat162float(hi));
}

// ---------------- kNN (4 queries per thread) ---------------------------------
__global__ __launch_bounds__(256) void knn_kernel(
    const float* __restrict__ xyz1, const float* __restrict__ xyz2)
{
    __shared__ float4 sp[S_];
    const int b = blockIdx.y;
    const int t = threadIdx.x;
    for (int s = t; s < S_; s += 256) {
        const float* p = xyz2 + ((size_t)b * S_ + s) * 3;
        sp[s] = make_float4(p[0], p[1], p[2], 0.0f);
    }
    __syncthreads();

    const int nb = blockIdx.x * 1024 + t;
    float qx[4], qy[4], qz[4];
    float d0[4], d1[4], d2[4];
    int   i0[4], i1[4], i2[4];
    #pragma unroll
    for (int j = 0; j < 4; j++) {
        const float* q = xyz1 + ((size_t)b * N_ + nb + j * 256) * 3;
        qx[j] = q[0]; qy[j] = q[1]; qz[j] = q[2];
        d0[j] = 3.4e38f; d1[j] = 3.4e38f; d2[j] = 3.4e38f;
        i0[j] = 0; i1[j] = 0; i2[j] = 0;
    }
    #pragma unroll 2
    for (int s = 0; s < S_; s++) {
        float4 p = sp[s];
        #pragma unroll
        for (int j = 0; j < 4; j++) {
            float dx = qx[j] - p.x, dy = qy[j] - p.y, dz = qz[j] - p.z;
            float d = fmaf(dz, dz, fmaf(dy, dy, dx * dx));
            if (d < d2[j]) {
                if (d < d1[j]) {
                    d2[j] = d1[j]; i2[j] = i1[j];
                    if (d < d0[j]) { d1[j] = d0[j]; i1[j] = i0[j]; d0[j] = d; i0[j] = s; }
                    else           { d1[j] = d;  i1[j] = s; }
                } else { d2[j] = d; i2[j] = s; }
            }
        }
    }
    #pragma unroll
    for (int j = 0; j < 4; j++) {
        float a = fmaxf(d0[j], 1e-10f), bb = fmaxf(d1[j], 1e-10f), c = fmaxf(d2[j], 1e-10f);
        float w0 = 1.0f / a, w1 = 1.0f / bb, w2 = 1.0f / c;
        float sw = w0 + w1 + w2;
        size_t base = ((size_t)b * N_ + nb + j * 256) * 3;
        g_idx[base] = i0[j]; g_idx[base + 1] = i1[j]; g_idx[base + 2] = i2[j];
        g_w[base] = w0 / sw; g_w[base + 1] = w1 / sw; g_w[base + 2] = w2 / sw;
    }
}

// ---------------- transpose points2 [B][C][S] -> [B][S][C] --------------------
__global__ void transpose_p2_kernel(const float* __restrict__ p2)
{
    __shared__ float tile[32][33];
    const int b  = blockIdx.z;
    const int s0 = blockIdx.x * 32;
    const int c0 = blockIdx.y * 32;
    #pragma unroll
    for (int r = 0; r < 4; r++) {
        int c = c0 + threadIdx.y + r * 8;
        tile[threadIdx.y + r * 8][threadIdx.x] =
            p2[((size_t)b * C2_ + c) * S_ + s0 + threadIdx.x];
    }
    __syncthreads();
    #pragma unroll
    for (int r = 0; r < 4; r++) {
        int s = s0 + threadIdx.y + r * 8;
        g_p2t[((size_t)b * S_ + s) * C2_ + c0 + threadIdx.x] =
            tile[threadIdx.x][threadIdx.y + r * 8];
    }
}

// ---------------- gather + weighted sum -> xcat channels [0,256) --------------
__global__ __launch_bounds__(256) void gather_kernel()
{
    const int b  = blockIdx.y;
    const int n0 = blockIdx.x * 32;
    const int t  = threadIdx.x;          // channel
    #pragma unroll 2
    for (int nl = 0; nl < 32; nl++) {
        size_t base = ((size_t)b * N_ + n0 + nl) * 3;
        int i0 = g_idx[base], i1 = g_idx[base + 1], i2 = g_idx[base + 2];
        float w0 = g_w[base], w1 = g_w[base + 1], w2 = g_w[base + 2];
        const float* r0 = g_p2t + ((size_t)b * S_ + i0) * C2_;
        const float* r1 = g_p2t + ((size_t)b * S_ + i1) * C2_;
        const float* r2 = g_p2t + ((size_t)b * S_ + i2) * C2_;
        float v = fmaf(w2, r2[t], fmaf(w1, r1[t], w0 * r0[t]));
        __nv_bfloat16 hi, lo; bf16_split(v, hi, lo);
        size_t o = ((size_t)b * N_ + n0 + nl) * K1_ + t;
        g_xh[o] = hi; g_xl[o] = lo;
    }
}

// ---------------- points1 transpose+split -> xcat channels [256,384) ----------
__global__ void p1t_kernel(const float* __restrict__ p1)
{
    __shared__ float tile[32][33];
    const int b  = blockIdx.z;
    const int n0 = blockIdx.x * 32;
    const int c0 = blockIdx.y * 32;
    #pragma unroll
    for (int r = 0; r < 4; r++) {
        int c = c0 + threadIdx.y + r * 8;
        tile[threadIdx.y + r * 8][threadIdx.x] =
            p1[((size_t)b * C1_ + c) * N_ + n0 + threadIdx.x];
    }
    __syncthreads();
    #pragma unroll
    for (int r = 0; r < 4; r++) {
        int n = n0 + threadIdx.y + r * 8;
        float v = tile[threadIdx.x][threadIdx.y + r * 8];
        __nv_bfloat16 hi, lo; bf16_split(v, hi, lo);
        size_t o = ((size_t)b * N_ + n) * K1_ + 256 + c0 + threadIdx.x;
        g_xh[o] = hi; g_xl[o] = lo;
    }
}

// ---------------- weight split -------------------------------------------------
__global__ void wsplit_kernel(const float* __restrict__ w,
                              __nv_bfloat16* __restrict__ hi,
                              __nv_bfloat16* __restrict__ lo, int n)
{
    int i = blockIdx.x * 256 + threadIdx.x;
    if (i < n) {
        __nv_bfloat16 h, l; bf16_split(w[i], h, l);
        hi[i] = h; lo[i] = l;
    }
}

// ---------------- mma.sync bf16 GEMM (3-term compensation) --------------------
// D[m 0..255][n tile 128] = sum_k W[m][k]*X[n][k]; W,X split hi/lo bf16.
// CTA: 256 thr = 8 warps (4 in M x 2 in N). Warp tile 64x64.
// Epilogue: y[(b*N+n)*256+m] = D + bias; per-CTA per-channel sum/sumsq.
template<int KDIM>
__global__ __launch_bounds__(256) void gemm_mma(
    const __nv_bfloat16* __restrict__ Ahi, const __nv_bfloat16* __restrict__ Alo,
    const __nv_bfloat16* __restrict__ Bhi, const __nv_bfloat16* __restrict__ Blo,
    const float* __restrict__ bias, float* __restrict__ Y,
    float* __restrict__ psum, float* __restrict__ pssq)
{
    constexpr int NS = KDIM / 32;                 // K stages of 32
    constexpr uint32_t PITCH  = 80;               // smem bytes/row: 64B data + 16B pad
    constexpr uint32_t OFF_AL = 256u * PITCH;     // 20480
    constexpr uint32_t OFF_BH = 2u * 256u * PITCH;// 40960
    constexpr uint32_t BVSZ   = 128u * PITCH;     // 10240
    constexpr uint32_t STAGE  = OFF_BH + 2u * BVSZ; // 61440

    extern __shared__ char sdyn[];
    __shared__ float sm_s[2][256], sm_q[2][256];

    const int tid  = threadIdx.x;
    const int lane = tid & 31, wid = tid >> 5;
    const int mw   = wid & 3;        // M block of 64
    const int nw   = wid >> 2;       // N block of 64
    const int b    = blockIdx.y;
    const int n0   = blockIdx.x * 128;
    const size_t bn0 = (size_t)b * N_ + n0;
    const uint32_t sb0 = smem_u32(sdyn);

    auto load_stage = [&](int kt, int buf) {
        uint32_t base = sb0 + (uint32_t)buf * STAGE;
        #pragma unroll
        for (int i = 0; i < 8; i++) {              // A: 2 variants x 256 rows x 4 chunks
            int c = tid + i * 256;
            int var = c >> 10, row = (c >> 2) & 255, ch = c & 3;
            const __nv_bfloat16* src = (var ? Alo : Ahi)
                + (size_t)row * KDIM + kt + ch * 8;
            cpa16(base + (uint32_t)var * OFF_AL + (uint32_t)row * PITCH + ch * 16, src);
        }
        #pragma unroll
        for (int i = 0; i < 4; i++) {              // B: 2 variants x 128 rows x 4 chunks
            int c = tid + i * 256;
            int var = c >> 9, row = (c >> 2) & 127, ch = c & 3;
            const __nv_bfloat16* src = (var ? Blo : Bhi)
                + (bn0 + row) * KDIM + kt + ch * 8;
            cpa16(base + OFF_BH + (uint32_t)var * BVSZ + (uint32_t)row * PITCH + ch * 16, src);
        }
        CP_COMMIT();
    };

    float acc[4][8][4] = {};

    load_stage(0, 0);

    #pragma unroll 1
    for (int s = 0; s < NS; s++) {
        if (s + 1 < NS) { load_stage((s + 1) * 32, (s + 1) & 1); CP_WAIT1(); }
        else            { CP_WAIT0(); }
        __syncthreads();

        uint32_t base = sb0 + (uint32_t)(s & 1) * STAGE;
        #pragma unroll
        for (int ks = 0; ks < 2; ks++) {
            uint32_t a[2][4][4];
            #pragma unroll
            for (int var = 0; var < 2; var++)
                #pragma unroll
                for (int mt = 0; mt < 4; mt++) {
                    uint32_t row = (uint32_t)(mw * 64 + mt * 16 + (lane & 15));
                    ldsm4(base + (uint32_t)var * OFF_AL + row * PITCH
                          + ks * 32 + ((lane >> 4) << 4), a[var][mt]);
                }
            #pragma unroll
            for (int ntp = 0; ntp < 4; ntp++) {
                uint32_t rowB = (uint32_t)(nw * 64 + ntp * 16
                               + ((lane >> 4) << 3) + (lane & 7));
                uint32_t adh = base + OFF_BH + rowB * PITCH
                             + ks * 32 + (((lane >> 3) & 1) << 4);
                uint32_t bh[4], bl[4];
                ldsm4(adh, bh);
                ldsm4(adh + BVSZ, bl);
                #pragma unroll
                for (int h = 0; h < 2; h++) {
                    int nt = ntp * 2 + h;
                    #pragma unroll
                    for (int mt = 0; mt < 4; mt++) {
                        mma16816(acc[mt][nt], a[0][mt], &bh[h * 2]);
                        mma16816(acc[mt][nt], a[1][mt], &bh[h * 2]);
                        mma16816(acc[mt][nt], a[0][mt], &bl[h * 2]);
                    }
                }
            }
        }
        __syncthreads();
    }

    // epilogue
    const int r = lane >> 2;
    float csum[8] = {}, cssq[8] = {};
    #pragma unroll
    for (int mt = 0; mt < 4; mt++) {
        const int m0 = mw * 64 + mt * 16 + r;
        const float bv0 = bias[m0], bv1 = bias[m0 + 8];
        #pragma unroll
        for (int nt = 0; nt < 8; nt++) {
            float* c = acc[mt][nt];
            size_t nb = bn0 + nw * 64 + nt * 8 + (lane & 3) * 2;
            float v0 = c[0] + bv0, v1 = c[1] + bv0;
            float v2 = c[2] + bv1, v3 = c[3] + bv1;
            Y[nb * 256 + m0]           = v0;
            Y[(nb + 1) * 256 + m0]     = v1;
            Y[nb * 256 + m0 + 8]       = v2;
            Y[(nb + 1) * 256 + m0 + 8] = v3;
            csum[mt * 2]     += v0 + v1;
            cssq[mt * 2]     += fmaf(v0, v0, v1 * v1);
            csum[mt * 2 + 1] += v2 + v3;
            cssq[mt * 2 + 1] += fmaf(v2, v2, v3 * v3);
        }
    }
    #pragma unroll
    for (int j = 0; j < 8; j++) {
        csum[j] += __shfl_xor_sync(0xffffffffu, csum[j], 1);
        csum[j] += __shfl_xor_sync(0xffffffffu, csum[j], 2);
        cssq[j] += __shfl_xor_sync(0xffffffffu, cssq[j], 1);
        cssq[j] += __shfl_xor_sync(0xffffffffu, cssq[j], 2);
    }
    if ((lane & 3) == 0) {
        #pragma unroll
        for (int mt = 0; mt < 4; mt++) {
            #pragma unroll
            for (int h = 0; h < 2; h++) {
                int ch = mw * 64 + mt * 16 + r + h * 8;
                sm_s[nw][ch] = csum[mt * 2 + h];
                sm_q[nw][ch] = cssq[mt * 2 + h];
            }
        }
    }
    __syncthreads();
    if (tid < 256) {
        int cta = blockIdx.x + blockIdx.y * gridDim.x;
        psum[tid * 1024 + cta] = sm_s[0][tid] + sm_s[1][tid];
        pssq[tid * 1024 + cta] = sm_q[0][tid] + sm_q[1][tid];
    }
}

// ---------------- BN fold: reduce 1024 partials per channel -------------------
__global__ __launch_bounds__(256) void stats2_kernel(
    const float* __restrict__ g, const float* __restrict__ beta,
    float* __restrict__ sb)
{
    const int o = blockIdx.x;
    const int t = threadIdx.x;
    float s = 0.0f, ss = 0.0f;
    #pragma unroll
    for (int i = 0; i < 4; i++) {
        s  += g_psum[o * 1024 + t * 4 + i];
        ss += g_pssq[o * 1024 + t * 4 + i];
    }
    const int lane = t & 31, w = t >> 5;
    #pragma unroll
    for (int off = 16; off; off >>= 1) {
        s  += __shfl_down_sync(0xffffffffu, s,  off);
        ss += __shfl_down_sync(0xffffffffu, ss, off);
    }
    __shared__ float rs[8], rss[8];
    if (lane == 0) { rs[w] = s; rss[w] = ss; }
    __syncthreads();
    if (t == 0) {
        float ts = 0.0f, tss = 0.0f;
        #pragma unroll
        for (int i = 0; i < 8; i++) { ts += rs[i]; tss += rss[i]; }
        float mean = ts * CNT_INV;
        float var  = tss * CNT_INV - mean * mean;
        float rstd = rsqrtf(var + BN_EPS);
        float sc = g[o] * rstd;
        sb[o]       = sc;
        sb[256 + o] = beta[o] - mean * sc;
    }
}

// ---------------- layer-1 norm + relu + bf16 split -> h -----------------------
__global__ __launch_bounds__(256) void splith_kernel(
    const float* __restrict__ y, const float* __restrict__ sb)
{
    size_t i4 = (size_t)blockIdx.x * 256 + threadIdx.x;   // over B*N*64
    int c4 = (int)(i4 & 63) * 4;
    float4 v  = ((const float4*)y)[i4];
    float4 sc = *(const float4*)(sb + c4);
    float4 bs = *(const float4*)(sb + 256 + c4);
    float a0 = fmaxf(fmaf(v.x, sc.x, bs.x), 0.0f);
    float a1 = fmaxf(fmaf(v.y, sc.y, bs.y), 0.0f);
    float a2 = fmaxf(fmaf(v.z, sc.z, bs.z), 0.0f);
    float a3 = fmaxf(fmaf(v.w, sc.w, bs.w), 0.0f);
    __nv_bfloat16 h0, l0, h1, l1, h2, l2, h3, l3;
    bf16_split(a0, h0, l0); bf16_split(a1, h1, l1);
    bf16_split(a2, h2, l2); bf16_split(a3, h3, l3);
    uint2 ph, pl;
    ph.x = (uint32_t)__bfloat16_as_ushort(h0) | ((uint32_t)__bfloat16_as_ushort(h1) << 16);
    ph.y = (uint32_t)__bfloat16_as_ushort(h2) | ((uint32_t)__bfloat16_as_ushort(h3) << 16);
    pl.x = (uint32_t)__bfloat16_as_ushort(l0) | ((uint32_t)__bfloat16_as_ushort(l1) << 16);
    pl.y = (uint32_t)__bfloat16_as_ushort(l2) | ((uint32_t)__bfloat16_as_ushort(l3) << 16);
    ((uint2*)g_hh)[i4] = ph;
    ((uint2*)g_hl)[i4] = pl;
}

// ---------------- final norm + relu + transpose -> out [B][256][N] ------------
__global__ __launch_bounds__(256) void outt_kernel(
    const float* __restrict__ y, const float* __restrict__ sb,
    float* __restrict__ out)
{
    __shared__ float tile[32][33];
    const int b  = blockIdx.z;
    const int n0 = blockIdx.x * 32;
    const int m0 = blockIdx.y * 32;
    const float sc = sb[m0 + threadIdx.x];
    const float bs = sb[256 + m0 + threadIdx.x];
    #pragma unroll
    for (int r = 0; r < 4; r++) {
        int n = n0 + threadIdx.y + r * 8;
        float v = y[((size_t)b * N_ + n) * 256 + m0 + threadIdx.x];
        tile[threadIdx.y + r * 8][threadIdx.x] = fmaxf(fmaf(v, sc, bs), 0.0f);
    }
    __syncthreads();
    #pragma unroll
    for (int r = 0; r < 4; r++) {
        int m = m0 + threadIdx.y + r * 8;
        out[((size_t)b * 256 + m) * N_ + n0 + threadIdx.x] =
            tile[threadIdx.x][threadIdx.y + r * 8];
    }
}

// ---------------- launcher ----------------------------------------------------
extern "C" void kernel_launch(void* const* d_in, const int* in_sizes, int n_in,
                              void* d_out, int out_size)
{
    const float* xyz1 = (const float*)d_in[0];
    const float* xyz2 = (const float*)d_in[1];
    const float* pts1 = (const float*)d_in[2];
    const float* pts2 = (const float*)d_in[3];
    const float* W0   = (const float*)d_in[4];
    const float* b0   = (const float*)d_in[5];
    const float* gg0  = (const float*)d_in[6];
    const float* be0  = (const float*)d_in[7];
    const float* W1   = (const float*)d_in[8];
    const float* b1   = (const float*)d_in[9];
    const float* gg1  = (const float*)d_in[10];
    const float* be1  = (const float*)d_in[11];
    float* out = (float*)d_out;

    __nv_bfloat16 *xh, *xl, *hh, *hl, *w0h, *w0l, *w1h, *w1l;
    float *y, *psum, *pssq, *sb1, *sb2;
    cudaGetSymbolAddress((void**)&xh,  g_xh);
    cudaGetSymbolAddress((void**)&xl,  g_xl);
    cudaGetSymbolAddress((void**)&hh,  g_hh);
    cudaGetSymbolAddress((void**)&hl,  g_hl);
    cudaGetSymbolAddress((void**)&w0h, g_w0h);
    cudaGetSymbolAddress((void**)&w0l, g_w0l);
    cudaGetSymbolAddress((void**)&w1h, g_w1h);
    cudaGetSymbolAddress((void**)&w1l, g_w1l);
    cudaGetSymbolAddress((void**)&y,   g_y);
    cudaGetSymbolAddress((void**)&psum, g_psum);
    cudaGetSymbolAddress((void**)&pssq, g_pssq);
    cudaGetSymbolAddress((void**)&sb1, g_sb1);
    cudaGetSymbolAddress((void**)&sb2, g_sb2);

    const int GEMM_SMEM = 2 * 61440;   // 120 KB double-buffered stages
    cudaFuncSetAttribute(gemm_mma<K1_>, cudaFuncAttributeMaxDynamicSharedMemorySize, GEMM_SMEM);
    cudaFuncSetAttribute(gemm_mma<O_>,  cudaFuncAttributeMaxDynamicSharedMemorySize, GEMM_SMEM);

    // prep
    wsplit_kernel<<<(O_ * K1_ + 255) / 256, 256>>>(W0, w0h, w0l, O_ * K1_);
    wsplit_kernel<<<(O_ * O_  + 255) / 256, 256>>>(W1, w1h, w1l, O_ * O_);
    knn_kernel<<<dim3(N_ / 1024, B_), 256>>>(xyz1, xyz2);
    transpose_p2_kernel<<<dim3(S_ / 32, C2_ / 32, B_), dim3(32, 8)>>>(pts2);
    gather_kernel<<<dim3(N_ / 32, B_), 256>>>();
    p1t_kernel<<<dim3(N_ / 32, C1_ / 32, B_), dim3(32, 8)>>>(pts1);

    // layer 1
    gemm_mma<K1_><<<dim3(N_ / 128, B_), 256, GEMM_SMEM>>>(w0h, w0l, xh, xl, b0, y, psum, pssq);
    stats2_kernel<<<256, 256>>>(gg0, be0, sb1);
    splith_kernel<<<(int)((size_t)B_ * N_ * 64 / 256), 256>>>(y, sb1);

    // layer 2
    gemm_mma<O_><<<dim3(N_ / 128, B_), 256, GEMM_SMEM>>>(w1h, w1l, hh, hl, b1, y, psum, pssq);
    stats2_kernel<<<256, 256>>>(gg1, be1, sb2);

    // output
    outt_kernel<<<dim3(N_ / 32, 8, B_), dim3(32, 8)>>>(y, sb2, out);
}